// round 8
// baseline (speedup 1.0000x reference)
#include <cuda_runtime.h>

// ============================================================================
// LSTMDecoder: 2-layer LSTM (H=1024, B=2, T=1023) + CE loss, fully fused.
//
// Structure:
//   init_kernel      : zero states, convert ids (int32/int64 auto-detect),
//                      mask sum reduction.
//   precompute       : base[b][4096] = cond[b]@Wih0[:, :1024]^T + bih0 + bhh0
//                      table[c][4096] = emb[c]@Wih0[:, 1024:]^T   (vocab=30!)
//                      bias1[4096]    = bih1 + bhh1
//   lstm_persist     : persistent kernel, 148 CTAs, software grid barrier.
//     Phase k: L0[k] (k<=1022)  ||  L1[k-1] (1<=k<=1023)
//              || logits[k-2] (2<=k<=1024) || nll[k-3] (3<=k<=1025)
//     Weights stream from L2 (48MB/phase, fits 126MB L2).
//     Cross-block state via __ldcg/__stcg (L1 not coherent across SMs).
// ============================================================================

#define NBLK        148
#define LSTM_BLOCKS 128
#define HDIM        1024
#define NGATE       4096
#define NCLS        30
#define NB          2
#define SEQ         1024
#define NT          1023      // timesteps
#define NPHASE      1026      // k = 0..1025

__device__ float g_base[NB][NGATE];
__device__ float g_table[NCLS][NGATE];
__device__ float g_bias1[NGATE];
__device__ float g_h0[2][NB][HDIM];
__device__ float g_h1[2][NB][HDIM];
__device__ float g_logits[2][NB][NCLS];
__device__ int   g_ids[NB][SEQ];
__device__ float g_masksum;
__device__ unsigned g_barcnt;   // zero-init, self-restoring across replays
__device__ unsigned g_bargen;

__device__ __forceinline__ float sigm(float x)   { return 1.0f / (1.0f + __expf(-x)); }
__device__ __forceinline__ float tanh_f(float x) { return 1.0f - 2.0f / (1.0f + __expf(2.0f * x)); }

#define WRED(v) { \
  v += __shfl_xor_sync(0xffffffffu, (v), 16); \
  v += __shfl_xor_sync(0xffffffffu, (v), 8);  \
  v += __shfl_xor_sync(0xffffffffu, (v), 4);  \
  v += __shfl_xor_sync(0xffffffffu, (v), 2);  \
  v += __shfl_xor_sync(0xffffffffu, (v), 1);  \
}

#define DOT4(acc, w4, h4) \
  acc = fmaf((w4).x,(h4).x, fmaf((w4).y,(h4).y, fmaf((w4).z,(h4).z, fmaf((w4).w,(h4).w,(acc)))));

__device__ __forceinline__ void grid_barrier() {
  __syncthreads();
  __threadfence();   // release our g_h*/g_logits stores before arriving
  if (threadIdx.x == 0) {
    unsigned gen = *((volatile unsigned*)&g_bargen);
    if (atomicAdd(&g_barcnt, 1u) == NBLK - 1u) {
      atomicExch(&g_barcnt, 0u);
      __threadfence();
      atomicAdd(&g_bargen, 1u);
    } else {
      while (*((volatile unsigned*)&g_bargen) == gen) { }
    }
  }
  __syncthreads();
}

// ---------------------------------------------------------------------------
__global__ __launch_bounds__(256) void init_kernel(const int* __restrict__ ids_raw,
                                                   const float* __restrict__ mask) {
  const int tid = threadIdx.x;
  const int gid = blockIdx.x * 256 + tid;    // grid = 8 blocks -> 2048 threads
  float* h0 = (float*)g_h0;
  float* h1 = (float*)g_h1;
  for (int i = gid; i < 2 * NB * HDIM; i += 2048) { h0[i] = 0.0f; h1[i] = 0.0f; }

  if (blockIdx.x == 0) {
    // --- ids dtype detection + conversion (block 0 only) ---
    // If int64: viewing as int32, all odd words (high halves) of the first
    // 1024 ids are 0 (values in [0,30)). If int32: odd words are random ids,
    // virtually surely some nonzero.
    __shared__ int s_odd;
    __shared__ float red[256];
    if (tid == 0) s_odd = 0;
    __syncthreads();
    int loc = 0;
    for (int i = tid; i < NB * SEQ; i += 256) if (i & 1) loc |= ids_raw[i];
    if (loc) atomicOr(&s_odd, 1);
    __syncthreads();
    const bool is64 = (s_odd == 0);
    int* idst = (int*)g_ids;
    for (int i = tid; i < NB * SEQ; i += 256) {
      idst[i] = is64 ? (int)(((const long long*)ids_raw)[i]) : ids_raw[i];
    }
    // --- mask[:, 1:] sum ---
    float s = 0.0f;
    for (int i = tid; i < NB * (SEQ - 1); i += 256) {
      int b = i / (SEQ - 1), p = i - b * (SEQ - 1);
      s += mask[b * SEQ + 1 + p];
    }
    red[tid] = s;
    __syncthreads();
    for (int off = 128; off > 0; off >>= 1) {
      if (tid < off) red[tid] += red[tid + off];
      __syncthreads();
    }
    if (tid == 0) g_masksum = red[0];
  }
}

// ---------------------------------------------------------------------------
__global__ __launch_bounds__(256) void precompute(
    const float* __restrict__ cond, const float* __restrict__ emb,
    const float* __restrict__ Wih0, const float* __restrict__ bih0,
    const float* __restrict__ bhh0, const float* __restrict__ bih1,
    const float* __restrict__ bhh1) {
  __shared__ float smc[NB * HDIM];
  __shared__ float sme[NCLS * 128];
  const int tid = threadIdx.x, wid = tid >> 5, lane = tid & 31;
  for (int i = tid; i < NB * HDIM; i += 256)  smc[i] = cond[i];
  for (int i = tid; i < NCLS * 128; i += 256) sme[i] = emb[i];
  __syncthreads();

  const int j = (blockIdx.x << 3) + wid;              // 512 blocks * 8 warps = 4096 rows
  const float* w = Wih0 + (size_t)j * 1152;

  float a0 = 0.0f, a1 = 0.0f;
  #pragma unroll
  for (int ch = 0; ch < 8; ch++) {
    const int idx = (ch << 7) + (lane << 2);
    const float4 w4 = *(const float4*)&w[idx];
    const float4 ca = *(const float4*)&smc[idx];
    const float4 cb = *(const float4*)&smc[HDIM + idx];
    DOT4(a0, w4, ca);
    DOT4(a1, w4, cb);
  }
  WRED(a0); WRED(a1);

  const float4 wt = *(const float4*)&w[HDIM + (lane << 2)];
  for (int c = 0; c < NCLS; c++) {
    const float4 e = *(const float4*)&sme[(c << 7) + (lane << 2)];
    float t = 0.0f;
    DOT4(t, wt, e);
    WRED(t);
    if (lane == 0) g_table[c][j] = t;
  }
  if (lane == 0) {
    const float bb = bih0[j] + bhh0[j];
    g_base[0][j] = a0 + bb;
    g_base[1][j] = a1 + bb;
    g_bias1[j]   = bih1[j] + bhh1[j];
  }
}

// ---------------------------------------------------------------------------
__global__ __launch_bounds__(256) void lstm_persist(
    const float* __restrict__ Whh0, const float* __restrict__ Wih1,
    const float* __restrict__ Whh1, const float* __restrict__ fcw,
    const float* __restrict__ fcb,  float* __restrict__ out) {
  __shared__ float sm_h0[NB * HDIM];   // h0[k-1] snapshot (both batches)
  __shared__ float sm_h1[NB * HDIM];   // h1[k-2] snapshot

  const int tid = threadIdx.x, bid = blockIdx.x;
  const int wid = tid >> 5, lane = tid & 31;
  const bool lstm = (bid < LSTM_BLOCKS);
  const int u  = (bid << 3) + wid;                 // hidden unit (lstm blocks)
  const int lw = ((bid - LSTM_BLOCKS) << 3) + wid; // loss warp id (aux blocks)

  // gate-row pointers (i,f,g,o rows: u, 1024+u, 2048+u, 3072+u)
  const float* w0i = Whh0 + (size_t)(u)        * HDIM;
  const float* w0f = Whh0 + (size_t)(1024 + u) * HDIM;
  const float* w0g = Whh0 + (size_t)(2048 + u) * HDIM;
  const float* w0o = Whh0 + (size_t)(3072 + u) * HDIM;
  const float* w1xi = Wih1 + (size_t)(u)        * HDIM;
  const float* w1xf = Wih1 + (size_t)(1024 + u) * HDIM;
  const float* w1xg = Wih1 + (size_t)(2048 + u) * HDIM;
  const float* w1xo = Wih1 + (size_t)(3072 + u) * HDIM;
  const float* w1hi = Whh1 + (size_t)(u)        * HDIM;
  const float* w1hf = Whh1 + (size_t)(1024 + u) * HDIM;
  const float* w1hg = Whh1 + (size_t)(2048 + u) * HDIM;
  const float* w1ho = Whh1 + (size_t)(3072 + u) * HDIM;

  float c0reg = 0.0f, c1reg = 0.0f;   // lane 0: batch 0, lane 1: batch 1
  float nll_acc = 0.0f;

  for (int k = 0; k < NPHASE; k++) {
    const int pc = k & 1, pp = pc ^ 1;

    // snapshot h0[k-1] (parity pp) and h1[k-2] (parity pc) to smem. L2-only
    // loads: values were written by other SMs; local L1 may be stale.
    {
      const float4* s0 = (const float4*)&g_h0[pp][0][0];
      const float4* s1 = (const float4*)&g_h1[pc][0][0];
      float4* d0 = (float4*)sm_h0;
      float4* d1 = (float4*)sm_h1;
      d0[tid]       = __ldcg(s0 + tid);
      d0[tid + 256] = __ldcg(s0 + tid + 256);
      d1[tid]       = __ldcg(s1 + tid);
      d1[tid + 256] = __ldcg(s1 + tid + 256);
    }
    __syncthreads();

    if (lstm) {
      // ---------------- Layer 0, time k ----------------
      if (k <= NT - 1) {
        float p0 = 0, p1 = 0, p2 = 0, p3 = 0;
        if (lane < 2) {   // prefetch preactivation inputs early (latency hidden)
          const int id = g_ids[lane][k];
          p0 = g_base[lane][u]        + g_table[id][u];
          p1 = g_base[lane][1024 + u] + g_table[id][1024 + u];
          p2 = g_base[lane][2048 + u] + g_table[id][2048 + u];
          p3 = g_base[lane][3072 + u] + g_table[id][3072 + u];
        }
        float ai0 = 0, af0 = 0, ag0 = 0, ao0 = 0;
        float ai1 = 0, af1 = 0, ag1 = 0, ao1 = 0;
        #pragma unroll
        for (int ch = 0; ch < 8; ch++) {
          const int idx = (ch << 7) + (lane << 2);
          const float4 ha = *(const float4*)&sm_h0[idx];
          const float4 hb = *(const float4*)&sm_h0[HDIM + idx];
          float4 w;
          w = *(const float4*)&w0i[idx]; DOT4(ai0, w, ha); DOT4(ai1, w, hb);
          w = *(const float4*)&w0f[idx]; DOT4(af0, w, ha); DOT4(af1, w, hb);
          w = *(const float4*)&w0g[idx]; DOT4(ag0, w, ha); DOT4(ag1, w, hb);
          w = *(const float4*)&w0o[idx]; DOT4(ao0, w, ha); DOT4(ao1, w, hb);
        }
        WRED(ai0); WRED(af0); WRED(ag0); WRED(ao0);
        WRED(ai1); WRED(af1); WRED(ag1); WRED(ao1);
        if (lane < 2) {
          const float iv = sigm(  (lane ? ai1 : ai0) + p0);
          const float fv = sigm(  (lane ? af1 : af0) + p1);
          const float gv = tanh_f((lane ? ag1 : ag0) + p2);
          const float ov = sigm(  (lane ? ao1 : ao0) + p3);
          c0reg = fv * c0reg + iv * gv;
          __stcg(&g_h0[pc][lane][u], ov * tanh_f(c0reg));
        }
      }
      // ---------------- Layer 1, time k-1 ----------------
      if (k >= 1 && k <= NT) {
        float p0 = 0, p1 = 0, p2 = 0, p3 = 0;
        if (lane < 2) {
          p0 = g_bias1[u];        p1 = g_bias1[1024 + u];
          p2 = g_bias1[2048 + u]; p3 = g_bias1[3072 + u];
        }
        float ai0 = 0, af0 = 0, ag0 = 0, ao0 = 0;
        float ai1 = 0, af1 = 0, ag1 = 0, ao1 = 0;
        #pragma unroll
        for (int ch = 0; ch < 8; ch++) {      // input = h0[k-1]
          const int idx = (ch << 7) + (lane << 2);
          const float4 ha = *(const float4*)&sm_h0[idx];
          const float4 hb = *(const float4*)&sm_h0[HDIM + idx];
          float4 w;
          w = *(const float4*)&w1xi[idx]; DOT4(ai0, w, ha); DOT4(ai1, w, hb);
          w = *(const float4*)&w1xf[idx]; DOT4(af0, w, ha); DOT4(af1, w, hb);
          w = *(const float4*)&w1xg[idx]; DOT4(ag0, w, ha); DOT4(ag1, w, hb);
          w = *(const float4*)&w1xo[idx]; DOT4(ao0, w, ha); DOT4(ao1, w, hb);
        }
        #pragma unroll
        for (int ch = 0; ch < 8; ch++) {      // recurrent = h1[k-2]
          const int idx = (ch << 7) + (lane << 2);
          const float4 ha = *(const float4*)&sm_h1[idx];
          const float4 hb = *(const float4*)&sm_h1[HDIM + idx];
          float4 w;
          w = *(const float4*)&w1hi[idx]; DOT4(ai0, w, ha); DOT4(ai1, w, hb);
          w = *(const float4*)&w1hf[idx]; DOT4(af0, w, ha); DOT4(af1, w, hb);
          w = *(const float4*)&w1hg[idx]; DOT4(ag0, w, ha); DOT4(ag1, w, hb);
          w = *(const float4*)&w1ho[idx]; DOT4(ao0, w, ha); DOT4(ao1, w, hb);
        }
        WRED(ai0); WRED(af0); WRED(ag0); WRED(ao0);
        WRED(ai1); WRED(af1); WRED(ag1); WRED(ao1);
        if (lane < 2) {
          const float iv = sigm(  (lane ? ai1 : ai0) + p0);
          const float fv = sigm(  (lane ? af1 : af0) + p1);
          const float gv = tanh_f((lane ? ag1 : ag0) + p2);
          const float ov = sigm(  (lane ? ao1 : ao0) + p3);
          c1reg = fv * c1reg + iv * gv;
          __stcg(&g_h1[pp][lane][u], ov * tanh_f(c1reg));
        }
      }
    } else {
      // ---------------- logits, time k-2 ----------------
      if (lw < 2 * NCLS && k >= 2 && k <= NT + 1) {
        const int cls = lw >> 1, b = lw & 1;
        const float* w = fcw + (size_t)cls * HDIM;
        float a = 0.0f;
        #pragma unroll
        for (int ch = 0; ch < 8; ch++) {
          const int idx = (ch << 7) + (lane << 2);
          const float4 w4 = *(const float4*)&w[idx];
          const float4 h4 = *(const float4*)&sm_h1[b * HDIM + idx];
          DOT4(a, w4, h4);
        }
        WRED(a);
        if (lane == 0) __stcg(&g_logits[pc][b][cls], a + fcb[cls]);
      }
      // ---------------- nll, time k-3 ----------------
      if (bid == NBLK - 1 && wid == 7 && lane < 2 && k >= 3) {
        const int t = k - 3;
        const float* lg = &g_logits[pp][lane][0];
        float mx = -1e30f;
        #pragma unroll
        for (int c = 0; c < NCLS; c++) mx = fmaxf(mx, __ldcg(lg + c));
        float se = 0.0f;
        #pragma unroll
        for (int c = 0; c < NCLS; c++) se += __expf(__ldcg(lg + c) - mx);
        const int tgt = g_ids[lane][t + 1];
        nll_acc += logf(se) + mx - __ldcg(lg + tgt);
      }
    }
    grid_barrier();
  }

  if (bid == NBLK - 1 && wid == 7) {
    const float n1 = __shfl_sync(0xffffffffu, nll_acc, 1);
    if (lane == 0) {
      const float tot  = nll_acc + n1;
      const float ce   = tot / (float)(NB * NT);     // mean over 2046 tokens
      const float ms   = g_masksum;
      const float loss = ce + (ce * ms) / ms;        // masked == ce (scalar ce)
      out[0] = loss;
    }
  }
}

// ---------------------------------------------------------------------------
extern "C" void kernel_launch(void* const* d_in, const int* in_sizes, int n_in,
                              void* d_out, int out_size) {
  (void)in_sizes; (void)n_in; (void)out_size;
  const int*   ids  = (const int*)d_in[0];     // int32 or int64, auto-detected
  const float* mask = (const float*)d_in[1];
  const float* cond = (const float*)d_in[2];
  const float* emb  = (const float*)d_in[3];
  const float* Wih0 = (const float*)d_in[4];
  const float* Whh0 = (const float*)d_in[5];
  const float* bih0 = (const float*)d_in[6];
  const float* bhh0 = (const float*)d_in[7];
  const float* Wih1 = (const float*)d_in[8];
  const float* Whh1 = (const float*)d_in[9];
  const float* bih1 = (const float*)d_in[10];
  const float* bhh1 = (const float*)d_in[11];
  const float* fcw  = (const float*)d_in[12];
  const float* fcb  = (const float*)d_in[13];

  init_kernel<<<8, 256>>>(ids, mask);
  precompute<<<512, 256>>>(cond, emb, Wih0, bih0, bhh0, bih1, bhh1);
  lstm_persist<<<NBLK, 256>>>(Whh0, Wih1, Whh1, fcw, fcb, (float*)d_out);
}